// round 1
// baseline (speedup 1.0000x reference)
#include <cuda_runtime.h>
#include <cstdint>

// Problem constants
static constexpr int TOK    = 4096;   // B*S
static constexpr int SEQ    = 2048;
static constexpr int DMODEL = 1024;
static constexpr int NHEADS = 16;
static constexpr int DFFN   = 4096;

// ---------------------------------------------------------------------------
// Device scratch (allocation-free rule: __device__ globals)
// ---------------------------------------------------------------------------
__device__ float g_Q [(size_t)TOK * DMODEL];
__device__ float g_K [(size_t)TOK * DMODEL];
__device__ float g_V [(size_t)TOK * DMODEL];
__device__ float g_S [(size_t)2 * NHEADS * SEQ * SEQ];   // 512 MB scores
__device__ float g_C [(size_t)TOK * DMODEL];             // ctx
__device__ float g_AO[(size_t)TOK * DMODEL];             // attn_out
__device__ float g_X1[(size_t)TOK * DMODEL];             // LN1 out
__device__ float g_H [(size_t)TOK * DFFN];               // relu(x W1 + b1)
__device__ float g_FF[(size_t)TOK * DMODEL];             // ff out

// ---------------------------------------------------------------------------
// Helpers
// ---------------------------------------------------------------------------
__device__ __forceinline__ uint32_t f2tf(float f) {
    uint32_t u;
    asm("cvt.rna.tf32.f32 %0, %1;" : "=r"(u) : "f"(f));
    return u;
}
__device__ __forceinline__ void cp16(void* s, const void* g) {
    uint32_t sa = (uint32_t)__cvta_generic_to_shared(s);
    asm volatile("cp.async.cg.shared.global [%0], [%1], 16;" :: "r"(sa), "l"(g));
}
__device__ __forceinline__ void cp_commit() { asm volatile("cp.async.commit_group;"); }
template <int N> __device__ __forceinline__ void cp_wait() {
    asm volatile("cp.async.wait_group %0;" :: "n"(N));
}
__device__ __forceinline__ void mma8(float* c, const uint32_t* a, const uint32_t* b) {
    asm volatile(
        "mma.sync.aligned.m16n8k8.row.col.f32.tf32.tf32.f32 "
        "{%0,%1,%2,%3},{%4,%5,%6,%7},{%8,%9},{%0,%1,%2,%3};"
        : "+f"(c[0]), "+f"(c[1]), "+f"(c[2]), "+f"(c[3])
        : "r"(a[0]), "r"(a[1]), "r"(a[2]), "r"(a[3]), "r"(b[0]), "r"(b[1]));
}

// Block-wide reductions (256 threads = 8 warps)
__device__ __forceinline__ float bred_sum(float v) {
    __shared__ float sh[8];
    #pragma unroll
    for (int o = 16; o > 0; o >>= 1) v += __shfl_xor_sync(0xffffffffu, v, o);
    if ((threadIdx.x & 31) == 0) sh[threadIdx.x >> 5] = v;
    __syncthreads();
    float r = sh[0];
    #pragma unroll
    for (int i = 1; i < 8; i++) r += sh[i];
    __syncthreads();
    return r;
}
__device__ __forceinline__ float bred_max(float v) {
    __shared__ float sh[8];
    #pragma unroll
    for (int o = 16; o > 0; o >>= 1) v = fmaxf(v, __shfl_xor_sync(0xffffffffu, v, o));
    if ((threadIdx.x & 31) == 0) sh[threadIdx.x >> 5] = v;
    __syncthreads();
    float r = sh[0];
    #pragma unroll
    for (int i = 1; i < 8; i++) r = fmaxf(r, sh[i]);
    __syncthreads();
    return r;
}

// ---------------------------------------------------------------------------
// TF32 GEMM.
//   C[M,N] = epilogue( A[M,K] * B + bias ),  A row-major.
//   BNK=false: B is [K,N] row-major.  BNK=true: B is [N,K] row-major (A*B^T).
//   Batched via blockIdx.z with split outer/inner strides (z = zo*nh + zi).
//   Epilogue: v = (acc + bias[n]) * alpha; optional ReLU.
//   All problem dims divide tiles exactly -> no bounds checks.
// ---------------------------------------------------------------------------
template <int BM, int BN, int BK, int WM, int WN, bool BNK, bool RELU>
__global__ void __launch_bounds__(256)
gemm_k(const float* __restrict__ A, const float* __restrict__ B,
       const float* __restrict__ bias, float* __restrict__ C,
       int Kdim, int lda, int ldb, int ldc,
       int nh, long sAo, long sAi, long sBo, long sBi, long sCo, long sCi,
       float alpha)
{
    constexpr int WARPS_M = BM / WM, WARPS_N = BN / WN;
    constexpr int NTH = WARPS_M * WARPS_N * 32;
    static_assert(NTH == 256, "thread count");
    constexpr int MF = WM / 16, NF = WN / 8;
    constexpr int LDAS = BK + 4;                 // (4r+k)%32 conflict-free
    constexpr int LDBS = BNK ? (BK + 4) : (BN + 8);
    constexpr int ASZ = BM * LDAS;
    constexpr int BSZ = BNK ? BN * LDBS : BK * LDBS;

    extern __shared__ float smem[];
    float* sA = smem;
    float* sB = smem + 2 * ASZ;

    {
        int z  = blockIdx.z;
        int zo = z / nh, zi = z - zo * nh;
        A += zo * sAo + zi * sAi;
        B += zo * sBo + zi * sBi;
        C += zo * sCo + zi * sCi;
    }
    const int m0 = blockIdx.y * BM, n0 = blockIdx.x * BN;
    const int tid = threadIdx.x, w = tid >> 5, l = tid & 31;
    const int wm = (w % WARPS_M) * WM, wn = (w / WARPS_M) * WN;

    float acc[MF][NF][4];
    #pragma unroll
    for (int i = 0; i < MF; i++)
        #pragma unroll
        for (int j = 0; j < NF; j++)
            #pragma unroll
            for (int q = 0; q < 4; q++) acc[i][j][q] = 0.f;

    const int KT = Kdim / BK;

    auto load_tiles = [&](int kt, int buf) {
        {   // A tile: [BM][BK] -> smem [m][k]
            const float* gA = A + (size_t)m0 * lda + kt * BK;
            float* s = sA + buf * ASZ;
            constexpr int V = BM * BK / 4, PR = BK / 4;
            #pragma unroll
            for (int i = 0; i < V / NTH; i++) {
                int idx = tid + i * NTH;
                int r = idx / PR, c = (idx - r * PR) * 4;
                cp16(&s[r * LDAS + c], gA + (size_t)r * lda + c);
            }
        }
        if constexpr (BNK) {   // B tile: [BN][BK] -> smem [n][k]
            const float* gB = B + (size_t)n0 * ldb + kt * BK;
            float* s = sB + buf * BSZ;
            constexpr int V = BN * BK / 4, PR = BK / 4;
            #pragma unroll
            for (int i = 0; i < V / NTH; i++) {
                int idx = tid + i * NTH;
                int r = idx / PR, c = (idx - r * PR) * 4;
                cp16(&s[r * LDBS + c], gB + (size_t)r * ldb + c);
            }
        } else {               // B tile: [BK][BN] -> smem [k][n]
            const float* gB = B + (size_t)kt * BK * ldb + n0;
            float* s = sB + buf * BSZ;
            constexpr int V = BK * BN / 4, PR = BN / 4;
            #pragma unroll
            for (int i = 0; i < V / NTH; i++) {
                int idx = tid + i * NTH;
                int r = idx / PR, c = (idx - r * PR) * 4;
                cp16(&s[r * LDBS + c], gB + (size_t)r * ldb + c);
            }
        }
    };

    load_tiles(0, 0);
    cp_commit();

    for (int kt = 0; kt < KT; kt++) {
        const int buf = kt & 1;
        if (kt + 1 < KT) {
            load_tiles(kt + 1, buf ^ 1);
            cp_commit();
            cp_wait<1>();
        } else {
            cp_wait<0>();
        }
        __syncthreads();

        const float* cA = sA + buf * ASZ;
        const float* cB = sB + buf * BSZ;
        #pragma unroll
        for (int ks = 0; ks < BK / 8; ks++) {
            const int k0 = ks * 8;
            uint32_t af[MF][4], bf[NF][2];
            #pragma unroll
            for (int i = 0; i < MF; i++) {
                int r = wm + i * 16 + (l >> 2);
                int kk = k0 + (l & 3);
                af[i][0] = f2tf(cA[r * LDAS + kk]);
                af[i][1] = f2tf(cA[(r + 8) * LDAS + kk]);
                af[i][2] = f2tf(cA[r * LDAS + kk + 4]);
                af[i][3] = f2tf(cA[(r + 8) * LDAS + kk + 4]);
            }
            #pragma unroll
            for (int j = 0; j < NF; j++) {
                int c = wn + j * 8 + (l >> 2);
                int kk = k0 + (l & 3);
                if constexpr (BNK) {
                    bf[j][0] = f2tf(cB[c * LDBS + kk]);
                    bf[j][1] = f2tf(cB[c * LDBS + kk + 4]);
                } else {
                    bf[j][0] = f2tf(cB[kk * LDBS + c]);
                    bf[j][1] = f2tf(cB[(kk + 4) * LDBS + c]);
                }
            }
            #pragma unroll
            for (int i = 0; i < MF; i++)
                #pragma unroll
                for (int j = 0; j < NF; j++)
                    mma8(acc[i][j], af[i], bf[j]);
        }
        __syncthreads();
    }

    // Epilogue
    #pragma unroll
    for (int i = 0; i < MF; i++) {
        #pragma unroll
        for (int j = 0; j < NF; j++) {
            int r = m0 + wm + i * 16 + (l >> 2);
            int c = n0 + wn + j * 8 + (l & 3) * 2;
            float b0 = bias ? bias[c] : 0.f;
            float b1 = bias ? bias[c + 1] : 0.f;
            float v0 = (acc[i][j][0] + b0) * alpha;
            float v1 = (acc[i][j][1] + b1) * alpha;
            float v2 = (acc[i][j][2] + b0) * alpha;
            float v3 = (acc[i][j][3] + b1) * alpha;
            if constexpr (RELU) {
                v0 = fmaxf(v0, 0.f); v1 = fmaxf(v1, 0.f);
                v2 = fmaxf(v2, 0.f); v3 = fmaxf(v3, 0.f);
            }
            C[(size_t)r * ldc + c]           = v0;
            C[(size_t)r * ldc + c + 1]       = v1;
            C[(size_t)(r + 8) * ldc + c]     = v2;
            C[(size_t)(r + 8) * ldc + c + 1] = v3;
        }
    }
}

// ---------------------------------------------------------------------------
// Row softmax over 2048-wide rows, in place. One block (256 thr) per row.
// ---------------------------------------------------------------------------
__global__ void __launch_bounds__(256) softmax2048(float* __restrict__ S) {
    float* p = S + (size_t)blockIdx.x * 2048;
    const int t = threadIdx.x;
    float4 x0 = ((float4*)p)[t];
    float4 x1 = ((float4*)p)[t + 256];
    float mx = fmaxf(fmaxf(fmaxf(x0.x, x0.y), fmaxf(x0.z, x0.w)),
                     fmaxf(fmaxf(x1.x, x1.y), fmaxf(x1.z, x1.w)));
    mx = bred_max(mx);
    x0.x = __expf(x0.x - mx); x0.y = __expf(x0.y - mx);
    x0.z = __expf(x0.z - mx); x0.w = __expf(x0.w - mx);
    x1.x = __expf(x1.x - mx); x1.y = __expf(x1.y - mx);
    x1.z = __expf(x1.z - mx); x1.w = __expf(x1.w - mx);
    float sm = x0.x + x0.y + x0.z + x0.w + x1.x + x1.y + x1.z + x1.w;
    sm = bred_sum(sm);
    float inv = 1.f / sm;
    x0.x *= inv; x0.y *= inv; x0.z *= inv; x0.w *= inv;
    x1.x *= inv; x1.y *= inv; x1.z *= inv; x1.w *= inv;
    ((float4*)p)[t]       = x0;
    ((float4*)p)[t + 256] = x1;
}

// ---------------------------------------------------------------------------
// out = LayerNorm(X + R) * g + b, rows of 1024. One block (256 thr) per row.
// ---------------------------------------------------------------------------
__global__ void __launch_bounds__(256)
add_ln1024(const float* __restrict__ X, const float* __restrict__ R,
           const float* __restrict__ gam, const float* __restrict__ bet,
           float* __restrict__ O)
{
    size_t row = blockIdx.x;
    const int t = threadIdx.x;                    // 256 threads, 1 float4 each
    float4 a = ((const float4*)(X + row * 1024))[t];
    float4 r = ((const float4*)(R + row * 1024))[t];
    float4 s;
    s.x = a.x + r.x; s.y = a.y + r.y; s.z = a.z + r.z; s.w = a.w + r.w;
    float sum = s.x + s.y + s.z + s.w;
    float sq  = s.x * s.x + s.y * s.y + s.z * s.z + s.w * s.w;
    sum = bred_sum(sum);
    sq  = bred_sum(sq);
    const float mu  = sum * (1.f / 1024.f);
    const float var = sq * (1.f / 1024.f) - mu * mu;
    const float rs  = rsqrtf(var + 1e-5f);
    float4 g4 = ((const float4*)gam)[t];
    float4 b4 = ((const float4*)bet)[t];
    float4 o;
    o.x = (s.x - mu) * rs * g4.x + b4.x;
    o.y = (s.y - mu) * rs * g4.y + b4.y;
    o.z = (s.z - mu) * rs * g4.z + b4.z;
    o.w = (s.w - mu) * rs * g4.w + b4.w;
    ((float4*)(O + row * 1024))[t] = o;
}

// ---------------------------------------------------------------------------
// Launch
// ---------------------------------------------------------------------------
extern "C" void kernel_launch(void* const* d_in, const int* in_sizes, int n_in,
                              void* d_out, int out_size)
{
    (void)in_sizes; (void)n_in; (void)out_size;
    const float* src = (const float*)d_in[0];
    const float* Wq  = (const float*)d_in[1];
    const float* bq  = (const float*)d_in[2];
    const float* Wk  = (const float*)d_in[3];
    const float* bk  = (const float*)d_in[4];
    const float* Wv  = (const float*)d_in[5];
    const float* bv  = (const float*)d_in[6];
    const float* Wo  = (const float*)d_in[7];
    const float* bo  = (const float*)d_in[8];
    const float* W1  = (const float*)d_in[9];
    const float* b1  = (const float*)d_in[10];
    const float* W2  = (const float*)d_in[11];
    const float* b2  = (const float*)d_in[12];
    const float* ln1g = (const float*)d_in[13];
    const float* ln1b = (const float*)d_in[14];
    const float* ln2g = (const float*)d_in[15];
    const float* ln2b = (const float*)d_in[16];
    float* out = (float*)d_out;

    float *Q, *K, *V, *S, *C, *AO, *X1, *H, *FF;
    cudaGetSymbolAddress((void**)&Q,  g_Q);
    cudaGetSymbolAddress((void**)&K,  g_K);
    cudaGetSymbolAddress((void**)&V,  g_V);
    cudaGetSymbolAddress((void**)&S,  g_S);
    cudaGetSymbolAddress((void**)&C,  g_C);
    cudaGetSymbolAddress((void**)&AO, g_AO);
    cudaGetSymbolAddress((void**)&X1, g_X1);
    cudaGetSymbolAddress((void**)&H,  g_H);
    cudaGetSymbolAddress((void**)&FF, g_FF);

    auto kn   = gemm_k<128, 128, 32, 32, 64, false, false>;  // C = A*B
    auto knr  = gemm_k<128, 128, 32, 32, 64, false, true>;   // + ReLU
    auto nkT  = gemm_k<128, 128, 32, 32, 64, true,  false>;  // C = A*B^T
    auto ctxk = gemm_k<128,  64, 32, 32, 32, false, false>;  // N=64 tile

    const int SM_KN  = (128 * 36 + 32 * 136) * 2 * 4;  // 71680 B
    const int SM_NK  = (128 * 36 + 128 * 36) * 2 * 4;  // 73728 B
    const int SM_CTX = (128 * 36 + 32 *  72) * 2 * 4;  // 55296 B
    cudaFuncSetAttribute(kn,   cudaFuncAttributeMaxDynamicSharedMemorySize, SM_KN);
    cudaFuncSetAttribute(knr,  cudaFuncAttributeMaxDynamicSharedMemorySize, SM_KN);
    cudaFuncSetAttribute(nkT,  cudaFuncAttributeMaxDynamicSharedMemorySize, SM_NK);
    cudaFuncSetAttribute(ctxk, cudaFuncAttributeMaxDynamicSharedMemorySize, SM_CTX);

    const dim3 blk(256);
    const long SQD = (long)SEQ * DMODEL;      // per-batch stride in Q/K/V/ctx
    const long SS  = (long)SEQ * SEQ;         // per-head stride in scores

    // 1-3: QKV projections (Q pre-scaled by 1/sqrt(d_k) = 0.125)
    kn<<<dim3(8, 32, 1), blk, SM_KN>>>(src, Wq, bq, Q, 1024, 1024, 1024, 1024,
                                       1, 0, 0, 0, 0, 0, 0, 0.125f);
    kn<<<dim3(8, 32, 1), blk, SM_KN>>>(src, Wk, bk, K, 1024, 1024, 1024, 1024,
                                       1, 0, 0, 0, 0, 0, 0, 1.f);
    kn<<<dim3(8, 32, 1), blk, SM_KN>>>(src, Wv, bv, V, 1024, 1024, 1024, 1024,
                                       1, 0, 0, 0, 0, 0, 0, 1.f);

    // 4: scores[b,h] = Q[b,h] * K[b,h]^T   (z = b*16 + h)
    nkT<<<dim3(16, 16, 32), blk, SM_NK>>>(Q, K, nullptr, S, 64, 1024, 1024, 2048,
                                          16, SQD, 64, SQD, 64, 16 * SS, SS, 1.f);

    // 5: softmax over each of the 65536 rows
    softmax2048<<<32 * 2048, blk>>>(S);

    // 6: ctx[b,h] = attn[b,h] * V[b,h]
    ctxk<<<dim3(1, 16, 32), blk, SM_CTX>>>(S, V, nullptr, C, 2048, 2048, 1024, 1024,
                                           16, 16 * SS, SS, SQD, 64, SQD, 64, 1.f);

    // 7: attn_out = ctx * Wo + bo
    kn<<<dim3(8, 32, 1), blk, SM_KN>>>(C, Wo, bo, AO, 1024, 1024, 1024, 1024,
                                       1, 0, 0, 0, 0, 0, 0, 1.f);

    // 8: x1 = LN(src + attn_out)
    add_ln1024<<<4096, blk>>>(src, AO, ln1g, ln1b, X1);

    // 9: h = relu(x1 * W1 + b1)
    knr<<<dim3(32, 32, 1), blk, SM_KN>>>(X1, W1, b1, H, 1024, 1024, 4096, 4096,
                                         1, 0, 0, 0, 0, 0, 0, 1.f);

    // 10: ff = h * W2 + b2
    kn<<<dim3(8, 32, 1), blk, SM_KN>>>(H, W2, b2, FF, 4096, 4096, 1024, 1024,
                                       1, 0, 0, 0, 0, 0, 0, 1.f);

    // 11: out = LN(x1 + ff)
    add_ln1024<<<4096, blk>>>(X1, FF, ln2g, ln2b, out);
}

// round 2
// speedup vs baseline: 1.1158x; 1.1158x over previous
#include <cuda_runtime.h>
#include <cstdint>

// Problem constants
static constexpr int TOK    = 4096;   // B*S
static constexpr int SEQ    = 2048;
static constexpr int DMODEL = 1024;
static constexpr int DFFN   = 4096;

// ---------------------------------------------------------------------------
// Device scratch (allocation-free rule: __device__ globals)
// ---------------------------------------------------------------------------
__device__ float g_Q [(size_t)TOK * DMODEL];
__device__ float g_K [(size_t)TOK * DMODEL];
__device__ float g_V [(size_t)TOK * DMODEL];
__device__ float g_C [(size_t)TOK * DMODEL];             // ctx (token-major)
__device__ float g_AO[(size_t)TOK * DMODEL];             // attn_out
__device__ float g_X1[(size_t)TOK * DMODEL];             // LN1 out
__device__ float g_H [(size_t)TOK * DFFN];               // relu(x W1 + b1)
__device__ float g_FF[(size_t)TOK * DMODEL];             // ff out

// ---------------------------------------------------------------------------
// Helpers
// ---------------------------------------------------------------------------
__device__ __forceinline__ uint32_t f2tf(float f) {
    uint32_t u;
    asm("cvt.rna.tf32.f32 %0, %1;" : "=r"(u) : "f"(f));
    return u;
}
__device__ __forceinline__ void cp16(void* s, const void* g) {
    uint32_t sa = (uint32_t)__cvta_generic_to_shared(s);
    asm volatile("cp.async.cg.shared.global [%0], [%1], 16;" :: "r"(sa), "l"(g));
}
__device__ __forceinline__ void cp_commit() { asm volatile("cp.async.commit_group;"); }
template <int N> __device__ __forceinline__ void cp_wait() {
    asm volatile("cp.async.wait_group %0;" :: "n"(N));
}
__device__ __forceinline__ void mma8(float* c, const uint32_t* a, const uint32_t* b) {
    asm volatile(
        "mma.sync.aligned.m16n8k8.row.col.f32.tf32.tf32.f32 "
        "{%0,%1,%2,%3},{%4,%5,%6,%7},{%8,%9},{%0,%1,%2,%3};"
        : "+f"(c[0]), "+f"(c[1]), "+f"(c[2]), "+f"(c[3])
        : "r"(a[0]), "r"(a[1]), "r"(a[2]), "r"(a[3]), "r"(b[0]), "r"(b[1]));
}

// Block-wide reductions (256 threads = 8 warps)
__device__ __forceinline__ float bred_sum(float v) {
    __shared__ float sh[8];
    #pragma unroll
    for (int o = 16; o > 0; o >>= 1) v += __shfl_xor_sync(0xffffffffu, v, o);
    if ((threadIdx.x & 31) == 0) sh[threadIdx.x >> 5] = v;
    __syncthreads();
    float r = sh[0];
    #pragma unroll
    for (int i = 1; i < 8; i++) r += sh[i];
    __syncthreads();
    return r;
}

// ---------------------------------------------------------------------------
// TF32 GEMM (dense projections / FFN).
//   C[M,N] = epilogue( A[M,K] * B + bias ),  A row-major, B [K,N] row-major.
// ---------------------------------------------------------------------------
template <int BM, int BN, int BK, int WM, int WN, bool RELU>
__global__ void __launch_bounds__(256)
gemm_k(const float* __restrict__ A, const float* __restrict__ B,
       const float* __restrict__ bias, float* __restrict__ C,
       int Kdim, int lda, int ldb, int ldc, float alpha)
{
    constexpr int WARPS_M = BM / WM, WARPS_N = BN / WN;
    constexpr int NTH = WARPS_M * WARPS_N * 32;
    static_assert(NTH == 256, "thread count");
    constexpr int MF = WM / 16, NF = WN / 8;
    constexpr int LDAS = BK + 4;                 // conflict-free A frag reads
    constexpr int LDBS = BN + 8;
    constexpr int ASZ = BM * LDAS;
    constexpr int BSZ = BK * LDBS;

    extern __shared__ float smem[];
    float* sA = smem;
    float* sB = smem + 2 * ASZ;

    const int m0 = blockIdx.y * BM, n0 = blockIdx.x * BN;
    const int tid = threadIdx.x, w = tid >> 5, l = tid & 31;
    const int wm = (w % WARPS_M) * WM, wn = (w / WARPS_M) * WN;

    float acc[MF][NF][4];
    #pragma unroll
    for (int i = 0; i < MF; i++)
        #pragma unroll
        for (int j = 0; j < NF; j++)
            #pragma unroll
            for (int q = 0; q < 4; q++) acc[i][j][q] = 0.f;

    const int KT = Kdim / BK;

    auto load_tiles = [&](int kt, int buf) {
        {   // A tile: [BM][BK]
            const float* gA = A + (size_t)m0 * lda + kt * BK;
            float* s = sA + buf * ASZ;
            constexpr int V = BM * BK / 4, PR = BK / 4;
            #pragma unroll
            for (int i = 0; i < V / NTH; i++) {
                int idx = tid + i * NTH;
                int r = idx / PR, c = (idx - r * PR) * 4;
                cp16(&s[r * LDAS + c], gA + (size_t)r * lda + c);
            }
        }
        {   // B tile: [BK][BN]
            const float* gB = B + (size_t)kt * BK * ldb + n0;
            float* s = sB + buf * BSZ;
            constexpr int V = BK * BN / 4, PR = BN / 4;
            #pragma unroll
            for (int i = 0; i < V / NTH; i++) {
                int idx = tid + i * NTH;
                int r = idx / PR, c = (idx - r * PR) * 4;
                cp16(&s[r * LDBS + c], gB + (size_t)r * ldb + c);
            }
        }
    };

    load_tiles(0, 0);
    cp_commit();

    for (int kt = 0; kt < KT; kt++) {
        const int buf = kt & 1;
        if (kt + 1 < KT) {
            load_tiles(kt + 1, buf ^ 1);
            cp_commit();
            cp_wait<1>();
        } else {
            cp_wait<0>();
        }
        __syncthreads();

        const float* cA = sA + buf * ASZ;
        const float* cB = sB + buf * BSZ;
        #pragma unroll
        for (int ks = 0; ks < BK / 8; ks++) {
            const int k0 = ks * 8;
            uint32_t af[MF][4], bf[NF][2];
            #pragma unroll
            for (int i = 0; i < MF; i++) {
                int r = wm + i * 16 + (l >> 2);
                int kk = k0 + (l & 3);
                af[i][0] = f2tf(cA[r * LDAS + kk]);
                af[i][1] = f2tf(cA[(r + 8) * LDAS + kk]);
                af[i][2] = f2tf(cA[r * LDAS + kk + 4]);
                af[i][3] = f2tf(cA[(r + 8) * LDAS + kk + 4]);
            }
            #pragma unroll
            for (int j = 0; j < NF; j++) {
                int c = wn + j * 8 + (l >> 2);
                int kk = k0 + (l & 3);
                bf[j][0] = f2tf(cB[kk * LDBS + c]);
                bf[j][1] = f2tf(cB[(kk + 4) * LDBS + c]);
            }
            #pragma unroll
            for (int i = 0; i < MF; i++)
                #pragma unroll
                for (int j = 0; j < NF; j++)
                    mma8(acc[i][j], af[i], bf[j]);
        }
        __syncthreads();
    }

    // Epilogue
    #pragma unroll
    for (int i = 0; i < MF; i++) {
        #pragma unroll
        for (int j = 0; j < NF; j++) {
            int r = m0 + wm + i * 16 + (l >> 2);
            int c = n0 + wn + j * 8 + (l & 3) * 2;
            float b0 = bias ? bias[c] : 0.f;
            float b1 = bias ? bias[c + 1] : 0.f;
            float v0 = (acc[i][j][0] + b0) * alpha;
            float v1 = (acc[i][j][1] + b1) * alpha;
            float v2 = (acc[i][j][2] + b0) * alpha;
            float v3 = (acc[i][j][3] + b1) * alpha;
            if constexpr (RELU) {
                v0 = fmaxf(v0, 0.f); v1 = fmaxf(v1, 0.f);
                v2 = fmaxf(v2, 0.f); v3 = fmaxf(v3, 0.f);
            }
            C[(size_t)r * ldc + c]           = v0;
            C[(size_t)r * ldc + c + 1]       = v1;
            C[(size_t)(r + 8) * ldc + c]     = v2;
            C[(size_t)(r + 8) * ldc + c + 1] = v3;
        }
    }
}

// ---------------------------------------------------------------------------
// Fused flash attention.
//   Per block: one (b,h), 128 query rows. Loop over 64-key K/V tiles.
//   ctx written token-major (same layout the old ctx GEMM produced).
//   Q pre-scaled by 1/sqrt(d_k) at the projection.
// Warp layout: warp w owns query rows [16w, 16w+16) fully (all 64 columns of
// S), so softmax row stats reduce within a lane quad (shfl_xor 1,2).
// ---------------------------------------------------------------------------
static constexpr int FA_LDK = 68;   // K/Q/P smem row stride (words)
static constexpr int FA_LDV = 72;   // V smem row stride (words)
static constexpr int FA_SMEM = (2 * 64 * FA_LDK + 2 * 64 * FA_LDV + 128 * FA_LDK) * 4;

__global__ void __launch_bounds__(256)
fa_kernel(const float* __restrict__ Q, const float* __restrict__ K,
          const float* __restrict__ V, float* __restrict__ C)
{
    constexpr int NIT = SEQ / 64;   // 32 key tiles
    extern __shared__ float smem[];
    float* sK  = smem;                          // [2][64][FA_LDK]
    float* sV  = smem + 2 * 64 * FA_LDK;        // [2][64][FA_LDV]
    float* sQP = smem + 2 * 64 * FA_LDK + 2 * 64 * FA_LDV;  // [128][FA_LDK]

    const int z = blockIdx.y;
    const int b = z >> 4, h = z & 15;
    const int q0 = blockIdx.x * 128;
    const float* Qg = Q + ((size_t)(b * SEQ + q0)) * 1024 + h * 64;
    const float* Kg = K + ((size_t)(b * SEQ)) * 1024 + h * 64;
    const float* Vg = V + ((size_t)(b * SEQ)) * 1024 + h * 64;

    const int tid = threadIdx.x, w = tid >> 5, l = tid & 31;
    const int lr = l >> 2, lq = l & 3;

    auto loadKV = [&](int n0, int buf) {
        float* dK = sK + buf * 64 * FA_LDK;
        float* dV = sV + buf * 64 * FA_LDV;
        #pragma unroll
        for (int i = 0; i < 4; i++) {           // 64 rows x 16 chunks = 1024
            int idx = tid + i * 256;
            int r = idx >> 4, c = (idx & 15) * 4;
            cp16(&dK[r * FA_LDK + c], Kg + (size_t)(n0 + r) * 1024 + c);
        }
        #pragma unroll
        for (int i = 0; i < 4; i++) {
            int idx = tid + i * 256;
            int r = idx >> 4, c = (idx & 15) * 4;
            cp16(&dV[r * FA_LDV + c], Vg + (size_t)(n0 + r) * 1024 + c);
        }
    };

    // Prologue: Q tile + first K/V tile
    #pragma unroll
    for (int i = 0; i < 8; i++) {               // 128 rows x 16 chunks = 2048
        int idx = tid + i * 256;
        int r = idx >> 4, c = (idx & 15) * 4;
        cp16(&sQP[r * FA_LDK + c], Qg + (size_t)r * 1024 + c);
    }
    cp_commit();
    loadKV(0, 0);
    cp_commit();

    cp_wait<1>();                                // Q ready
    __syncthreads();

    // Q fragments (converted once)
    uint32_t qf[8][4];
    #pragma unroll
    for (int t = 0; t < 8; t++) {
        int r = w * 16 + lr, c = t * 8 + lq;
        qf[t][0] = f2tf(sQP[r * FA_LDK + c]);
        qf[t][1] = f2tf(sQP[(r + 8) * FA_LDK + c]);
        qf[t][2] = f2tf(sQP[r * FA_LDK + c + 4]);
        qf[t][3] = f2tf(sQP[(r + 8) * FA_LDK + c + 4]);
    }

    float oacc[8][4];
    #pragma unroll
    for (int j = 0; j < 8; j++)
        #pragma unroll
        for (int q = 0; q < 4; q++) oacc[j][q] = 0.f;
    float mA = -1e30f, mB = -1e30f, lA = 0.f, lB = 0.f;

    float* sP = sQP + (size_t)w * 16 * FA_LDK;   // per-warp P patch (own rows)
    uint32_t* sPu = (uint32_t*)sP;

    for (int it = 0; it < NIT; it++) {
        const int buf = it & 1;
        __syncthreads();                         // done reading buf^1
        if (it + 1 < NIT) {
            loadKV((it + 1) * 64, buf ^ 1);
            cp_commit();
            cp_wait<1>();
        } else {
            cp_wait<0>();
        }
        __syncthreads();

        // Convert K,V tile fp32 -> tf32 in place (one pass, read by 8 warps)
        {
            uint32_t* kp = (uint32_t*)(sK + buf * 64 * FA_LDK);
            uint32_t* vp = (uint32_t*)(sV + buf * 64 * FA_LDV);
            #pragma unroll
            for (int i = 0; i < 16; i++) {
                int idx = tid + i * 256;         // 4096 elements per tile
                int r = idx >> 6, c = idx & 63;
                kp[r * FA_LDK + c] = f2tf(__uint_as_float(kp[r * FA_LDK + c]));
                vp[r * FA_LDV + c] = f2tf(__uint_as_float(vp[r * FA_LDV + c]));
            }
        }
        __syncthreads();

        const uint32_t* cK = (const uint32_t*)(sK + buf * 64 * FA_LDK);
        const uint32_t* cV = (const uint32_t*)(sV + buf * 64 * FA_LDV);

        // S = Q * K^T  (16 rows x 64 keys per warp)
        float s[8][4];
        #pragma unroll
        for (int j = 0; j < 8; j++)
            #pragma unroll
            for (int q = 0; q < 4; q++) s[j][q] = 0.f;
        #pragma unroll
        for (int ks = 0; ks < 8; ks++) {
            #pragma unroll
            for (int j = 0; j < 8; j++) {
                uint32_t bf[2];
                bf[0] = cK[(j * 8 + lr) * FA_LDK + ks * 8 + lq];
                bf[1] = cK[(j * 8 + lr) * FA_LDK + ks * 8 + lq + 4];
                mma8(s[j], qf[ks], bf);
            }
        }

        // Online softmax (rowA = l/4, rowB = l/4+8 within warp tile)
        float tmA = s[0][0], tmB = s[0][2];
        #pragma unroll
        for (int j = 0; j < 8; j++) {
            tmA = fmaxf(tmA, fmaxf(s[j][0], s[j][1]));
            tmB = fmaxf(tmB, fmaxf(s[j][2], s[j][3]));
        }
        tmA = fmaxf(tmA, __shfl_xor_sync(0xffffffffu, tmA, 1));
        tmA = fmaxf(tmA, __shfl_xor_sync(0xffffffffu, tmA, 2));
        tmB = fmaxf(tmB, __shfl_xor_sync(0xffffffffu, tmB, 1));
        tmB = fmaxf(tmB, __shfl_xor_sync(0xffffffffu, tmB, 2));

        float nmA = fmaxf(mA, tmA), nmB = fmaxf(mB, tmB);
        float sclA = __expf(mA - nmA), sclB = __expf(mB - nmB);
        mA = nmA; mB = nmB;

        float sumA = 0.f, sumB = 0.f;
        #pragma unroll
        for (int j = 0; j < 8; j++) {
            float p0 = __expf(s[j][0] - nmA);
            float p1 = __expf(s[j][1] - nmA);
            float p2 = __expf(s[j][2] - nmB);
            float p3 = __expf(s[j][3] - nmB);
            sumA += p0 + p1; sumB += p2 + p3;
            // write P to smem (tf32) for re-fragmenting as A of P*V
            *(uint2*)&sP[lr * FA_LDK + j * 8 + 2 * lq] =
                make_uint2(f2tf(p0), f2tf(p1));
            *(uint2*)&sP[(lr + 8) * FA_LDK + j * 8 + 2 * lq] =
                make_uint2(f2tf(p2), f2tf(p3));
        }
        sumA += __shfl_xor_sync(0xffffffffu, sumA, 1);
        sumA += __shfl_xor_sync(0xffffffffu, sumA, 2);
        sumB += __shfl_xor_sync(0xffffffffu, sumB, 1);
        sumB += __shfl_xor_sync(0xffffffffu, sumB, 2);
        lA = lA * sclA + sumA;
        lB = lB * sclB + sumB;

        // Rescale O accumulators
        #pragma unroll
        for (int j = 0; j < 8; j++) {
            oacc[j][0] *= sclA; oacc[j][1] *= sclA;
            oacc[j][2] *= sclB; oacc[j][3] *= sclB;
        }
        __syncwarp();

        // O += P * V   (k dim = 64 keys)
        #pragma unroll
        for (int ks = 0; ks < 8; ks++) {
            uint32_t pa[4];
            pa[0] = sPu[lr * FA_LDK + ks * 8 + lq];
            pa[1] = sPu[(lr + 8) * FA_LDK + ks * 8 + lq];
            pa[2] = sPu[lr * FA_LDK + ks * 8 + lq + 4];
            pa[3] = sPu[(lr + 8) * FA_LDK + ks * 8 + lq + 4];
            #pragma unroll
            for (int j = 0; j < 8; j++) {
                uint32_t bf[2];
                bf[0] = cV[(ks * 8 + lq) * FA_LDV + j * 8 + lr];
                bf[1] = cV[(ks * 8 + lq + 4) * FA_LDV + j * 8 + lr];
                mma8(oacc[j], pa, bf);
            }
        }
    }

    // Epilogue: normalize and write ctx (token-major, head-contig columns)
    const float invA = 1.f / lA, invB = 1.f / lB;
    const size_t rowA = (size_t)(b * SEQ + q0 + w * 16 + lr);
    #pragma unroll
    for (int j = 0; j < 8; j++) {
        int col = h * 64 + j * 8 + 2 * lq;
        *(float2*)&C[rowA * 1024 + col] =
            make_float2(oacc[j][0] * invA, oacc[j][1] * invA);
        *(float2*)&C[(rowA + 8) * 1024 + col] =
            make_float2(oacc[j][2] * invB, oacc[j][3] * invB);
    }
}

// ---------------------------------------------------------------------------
// out = LayerNorm(X + R) * g + b, rows of 1024. One block (256 thr) per row.
// ---------------------------------------------------------------------------
__global__ void __launch_bounds__(256)
add_ln1024(const float* __restrict__ X, const float* __restrict__ R,
           const float* __restrict__ gam, const float* __restrict__ bet,
           float* __restrict__ O)
{
    size_t row = blockIdx.x;
    const int t = threadIdx.x;
    float4 a = ((const float4*)(X + row * 1024))[t];
    float4 r = ((const float4*)(R + row * 1024))[t];
    float4 s;
    s.x = a.x + r.x; s.y = a.y + r.y; s.z = a.z + r.z; s.w = a.w + r.w;
    float sum = s.x + s.y + s.z + s.w;
    float sq  = s.x * s.x + s.y * s.y + s.z * s.z + s.w * s.w;
    sum = bred_sum(sum);
    sq  = bred_sum(sq);
    const float mu  = sum * (1.f / 1024.f);
    const float var = sq * (1.f / 1024.f) - mu * mu;
    const float rs  = rsqrtf(var + 1e-5f);
    float4 g4 = ((const float4*)gam)[t];
    float4 b4 = ((const float4*)bet)[t];
    float4 o;
    o.x = (s.x - mu) * rs * g4.x + b4.x;
    o.y = (s.y - mu) * rs * g4.y + b4.y;
    o.z = (s.z - mu) * rs * g4.z + b4.z;
    o.w = (s.w - mu) * rs * g4.w + b4.w;
    ((float4*)(O + row * 1024))[t] = o;
}

// ---------------------------------------------------------------------------
// Launch
// ---------------------------------------------------------------------------
extern "C" void kernel_launch(void* const* d_in, const int* in_sizes, int n_in,
                              void* d_out, int out_size)
{
    (void)in_sizes; (void)n_in; (void)out_size;
    const float* src = (const float*)d_in[0];
    const float* Wq  = (const float*)d_in[1];
    const float* bq  = (const float*)d_in[2];
    const float* Wk  = (const float*)d_in[3];
    const float* bk  = (const float*)d_in[4];
    const float* Wv  = (const float*)d_in[5];
    const float* bv  = (const float*)d_in[6];
    const float* Wo  = (const float*)d_in[7];
    const float* bo  = (const float*)d_in[8];
    const float* W1  = (const float*)d_in[9];
    const float* b1  = (const float*)d_in[10];
    const float* W2  = (const float*)d_in[11];
    const float* b2  = (const float*)d_in[12];
    const float* ln1g = (const float*)d_in[13];
    const float* ln1b = (const float*)d_in[14];
    const float* ln2g = (const float*)d_in[15];
    const float* ln2b = (const float*)d_in[16];
    float* out = (float*)d_out;

    float *Q, *K, *V, *C, *AO, *X1, *H, *FF;
    cudaGetSymbolAddress((void**)&Q,  g_Q);
    cudaGetSymbolAddress((void**)&K,  g_K);
    cudaGetSymbolAddress((void**)&V,  g_V);
    cudaGetSymbolAddress((void**)&C,  g_C);
    cudaGetSymbolAddress((void**)&AO, g_AO);
    cudaGetSymbolAddress((void**)&X1, g_X1);
    cudaGetSymbolAddress((void**)&H,  g_H);
    cudaGetSymbolAddress((void**)&FF, g_FF);

    auto kn  = gemm_k<128, 128, 32, 32, 64, false>;
    auto knr = gemm_k<128, 128, 32, 32, 64, true>;

    const int SM_KN = (128 * 36 + 32 * 136) * 2 * 4;  // 71680 B
    cudaFuncSetAttribute(kn,  cudaFuncAttributeMaxDynamicSharedMemorySize, SM_KN);
    cudaFuncSetAttribute(knr, cudaFuncAttributeMaxDynamicSharedMemorySize, SM_KN);
    cudaFuncSetAttribute(fa_kernel, cudaFuncAttributeMaxDynamicSharedMemorySize, FA_SMEM);

    const dim3 blk(256);

    // QKV projections (Q pre-scaled by 1/sqrt(d_k) = 0.125)
    kn<<<dim3(8, 32, 1), blk, SM_KN>>>(src, Wq, bq, Q, 1024, 1024, 1024, 1024, 0.125f);
    kn<<<dim3(8, 32, 1), blk, SM_KN>>>(src, Wk, bk, K, 1024, 1024, 1024, 1024, 1.f);
    kn<<<dim3(8, 32, 1), blk, SM_KN>>>(src, Wv, bv, V, 1024, 1024, 1024, 1024, 1.f);

    // Fused attention: scores + softmax + ctx
    fa_kernel<<<dim3(16, 32), blk, FA_SMEM>>>(Q, K, V, C);

    // attn_out = ctx * Wo + bo
    kn<<<dim3(8, 32, 1), blk, SM_KN>>>(C, Wo, bo, AO, 1024, 1024, 1024, 1024, 1.f);

    // x1 = LN(src + attn_out)
    add_ln1024<<<4096, blk>>>(src, AO, ln1g, ln1b, X1);

    // h = relu(x1 * W1 + b1)
    knr<<<dim3(32, 32, 1), blk, SM_KN>>>(X1, W1, b1, H, 1024, 1024, 4096, 4096, 1.f);

    // ff = h * W2 + b2
    kn<<<dim3(8, 32, 1), blk, SM_KN>>>(H, W2, b2, FF, 4096, 4096, 1024, 1024, 1.f);

    // out = LN(x1 + ff)
    add_ln1024<<<4096, blk>>>(X1, FF, ln2g, ln2b, out);
}

// round 3
// speedup vs baseline: 1.3163x; 1.1797x over previous
#include <cuda_runtime.h>
#include <cstdint>

// Problem constants
static constexpr int TOK    = 4096;   // B*S
static constexpr int SEQ    = 2048;
static constexpr int DMODEL = 1024;
static constexpr int DFFN   = 4096;

// ---------------------------------------------------------------------------
// Device scratch (allocation-free rule: __device__ globals)
// Buffers holding TF32 bit patterns are still declared float (bits reinterp).
// ---------------------------------------------------------------------------
__device__ float g_srcT[(size_t)TOK * DMODEL];           // tf32 src
__device__ float g_WqT [(size_t)DMODEL * DMODEL];
__device__ float g_WkT [(size_t)DMODEL * DMODEL];
__device__ float g_WvT [(size_t)DMODEL * DMODEL];
__device__ float g_WoT [(size_t)DMODEL * DMODEL];
__device__ float g_W1T [(size_t)DMODEL * DFFN];
__device__ float g_W2T [(size_t)DFFN * DMODEL];
__device__ float g_Q  [(size_t)TOK * DMODEL];            // tf32
__device__ float g_K  [(size_t)TOK * DMODEL];            // tf32
__device__ float g_V  [(size_t)TOK * DMODEL];            // tf32
__device__ float g_C  [(size_t)TOK * DMODEL];            // tf32 ctx
__device__ float g_AO [(size_t)TOK * DMODEL];            // fp32 attn_out
__device__ float g_X1 [(size_t)TOK * DMODEL];            // fp32 LN1 out
__device__ float g_X1T[(size_t)TOK * DMODEL];            // tf32 LN1 out
__device__ float g_H  [(size_t)TOK * DFFN];              // tf32 relu(xW1+b1)
__device__ float g_FF [(size_t)TOK * DMODEL];            // fp32 ff out

// ---------------------------------------------------------------------------
// Helpers
// ---------------------------------------------------------------------------
__device__ __forceinline__ uint32_t f2tf(float f) {
    uint32_t u;
    asm("cvt.rna.tf32.f32 %0, %1;" : "=r"(u) : "f"(f));
    return u;
}
__device__ __forceinline__ void cp16(void* s, const void* g) {
    uint32_t sa = (uint32_t)__cvta_generic_to_shared(s);
    asm volatile("cp.async.cg.shared.global [%0], [%1], 16;" :: "r"(sa), "l"(g));
}
__device__ __forceinline__ void cp_commit() { asm volatile("cp.async.commit_group;"); }
template <int N> __device__ __forceinline__ void cp_wait() {
    asm volatile("cp.async.wait_group %0;" :: "n"(N));
}
__device__ __forceinline__ void mma8(float* c, const uint32_t* a, const uint32_t* b) {
    asm volatile(
        "mma.sync.aligned.m16n8k8.row.col.f32.tf32.tf32.f32 "
        "{%0,%1,%2,%3},{%4,%5,%6,%7},{%8,%9},{%0,%1,%2,%3};"
        : "+f"(c[0]), "+f"(c[1]), "+f"(c[2]), "+f"(c[3])
        : "r"(a[0]), "r"(a[1]), "r"(a[2]), "r"(a[3]), "r"(b[0]), "r"(b[1]));
}

// Block-wide sum over 256 threads (8 warps)
__device__ __forceinline__ float bred_sum(float v) {
    __shared__ float sh[8];
    #pragma unroll
    for (int o = 16; o > 0; o >>= 1) v += __shfl_xor_sync(0xffffffffu, v, o);
    if ((threadIdx.x & 31) == 0) sh[threadIdx.x >> 5] = v;
    __syncthreads();
    float r = sh[0];
    #pragma unroll
    for (int i = 1; i < 8; i++) r += sh[i];
    __syncthreads();
    return r;
}

// ---------------------------------------------------------------------------
// fp32 -> tf32-bits converter (vectorized, grid-stride)
// ---------------------------------------------------------------------------
__global__ void __launch_bounds__(256)
cvt_tf32(const float* __restrict__ in, float* __restrict__ outb, int n4)
{
    for (int i = blockIdx.x * 256 + threadIdx.x; i < n4; i += gridDim.x * 256) {
        float4 v = ((const float4*)in)[i];
        uint4 u;
        u.x = f2tf(v.x); u.y = f2tf(v.y); u.z = f2tf(v.z); u.w = f2tf(v.w);
        ((uint4*)outb)[i] = u;
    }
}

// ---------------------------------------------------------------------------
// TF32 GEMM. A and B already hold tf32 bit patterns — no cvt in mainloop.
//   C[M,N] = epilogue( A[M,K] * B + bias ),  A row-major, B [K,N] row-major.
//   OTF: write result as tf32 bits (consumer is an mma A-operand).
// ---------------------------------------------------------------------------
template <int BM, int BN, int BK, int WM, int WN, bool RELU, bool OTF>
__global__ void __launch_bounds__(256, 2)
gemm_t(const float* __restrict__ A, const float* __restrict__ B,
       const float* __restrict__ bias, float* __restrict__ C,
       int Kdim, int lda, int ldb, int ldc, float alpha)
{
    constexpr int WARPS_M = BM / WM, WARPS_N = BN / WN;
    constexpr int NTH = WARPS_M * WARPS_N * 32;
    static_assert(NTH == 256, "thread count");
    constexpr int MF = WM / 16, NF = WN / 8;
    constexpr int LDAS = BK + 4;
    constexpr int LDBS = BN + 8;
    constexpr int ASZ = BM * LDAS;
    constexpr int BSZ = BK * LDBS;

    extern __shared__ float smem[];
    float* sA = smem;
    float* sB = smem + 2 * ASZ;

    const int m0 = blockIdx.y * BM, n0 = blockIdx.x * BN;
    const int tid = threadIdx.x, w = tid >> 5, l = tid & 31;
    const int wm = (w % WARPS_M) * WM, wn = (w / WARPS_M) * WN;

    float acc[MF][NF][4];
    #pragma unroll
    for (int i = 0; i < MF; i++)
        #pragma unroll
        for (int j = 0; j < NF; j++)
            #pragma unroll
            for (int q = 0; q < 4; q++) acc[i][j][q] = 0.f;

    const int KT = Kdim / BK;

    auto load_tiles = [&](int kt, int buf) {
        {   // A tile: [BM][BK]
            const float* gA = A + (size_t)m0 * lda + kt * BK;
            float* s = sA + buf * ASZ;
            constexpr int V = BM * BK / 4, PR = BK / 4;
            #pragma unroll
            for (int i = 0; i < V / NTH; i++) {
                int idx = tid + i * NTH;
                int r = idx / PR, c = (idx - r * PR) * 4;
                cp16(&s[r * LDAS + c], gA + (size_t)r * lda + c);
            }
        }
        {   // B tile: [BK][BN]
            const float* gB = B + (size_t)kt * BK * ldb + n0;
            float* s = sB + buf * BSZ;
            constexpr int V = BK * BN / 4, PR = BN / 4;
            #pragma unroll
            for (int i = 0; i < V / NTH; i++) {
                int idx = tid + i * NTH;
                int r = idx / PR, c = (idx - r * PR) * 4;
                cp16(&s[r * LDBS + c], gB + (size_t)r * ldb + c);
            }
        }
    };

    load_tiles(0, 0);
    cp_commit();

    for (int kt = 0; kt < KT; kt++) {
        const int buf = kt & 1;
        if (kt + 1 < KT) {
            load_tiles(kt + 1, buf ^ 1);
            cp_commit();
            cp_wait<1>();
        } else {
            cp_wait<0>();
        }
        __syncthreads();

        const uint32_t* cA = (const uint32_t*)(sA + buf * ASZ);
        const uint32_t* cB = (const uint32_t*)(sB + buf * BSZ);
        #pragma unroll
        for (int ks = 0; ks < BK / 8; ks++) {
            const int k0 = ks * 8;
            uint32_t af[MF][4], bf[NF][2];
            #pragma unroll
            for (int i = 0; i < MF; i++) {
                int r = wm + i * 16 + (l >> 2);
                int kk = k0 + (l & 3);
                af[i][0] = cA[r * LDAS + kk];
                af[i][1] = cA[(r + 8) * LDAS + kk];
                af[i][2] = cA[r * LDAS + kk + 4];
                af[i][3] = cA[(r + 8) * LDAS + kk + 4];
            }
            #pragma unroll
            for (int j = 0; j < NF; j++) {
                int c = wn + j * 8 + (l >> 2);
                int kk = k0 + (l & 3);
                bf[j][0] = cB[kk * LDBS + c];
                bf[j][1] = cB[(kk + 4) * LDBS + c];
            }
            #pragma unroll
            for (int i = 0; i < MF; i++)
                #pragma unroll
                for (int j = 0; j < NF; j++)
                    mma8(acc[i][j], af[i], bf[j]);
        }
        __syncthreads();
    }

    // Epilogue
    #pragma unroll
    for (int i = 0; i < MF; i++) {
        #pragma unroll
        for (int j = 0; j < NF; j++) {
            int r = m0 + wm + i * 16 + (l >> 2);
            int c = n0 + wn + j * 8 + (l & 3) * 2;
            float b0 = bias ? bias[c] : 0.f;
            float b1 = bias ? bias[c + 1] : 0.f;
            float v0 = (acc[i][j][0] + b0) * alpha;
            float v1 = (acc[i][j][1] + b1) * alpha;
            float v2 = (acc[i][j][2] + b0) * alpha;
            float v3 = (acc[i][j][3] + b1) * alpha;
            if constexpr (RELU) {
                v0 = fmaxf(v0, 0.f); v1 = fmaxf(v1, 0.f);
                v2 = fmaxf(v2, 0.f); v3 = fmaxf(v3, 0.f);
            }
            if constexpr (OTF) {
                v0 = __uint_as_float(f2tf(v0)); v1 = __uint_as_float(f2tf(v1));
                v2 = __uint_as_float(f2tf(v2)); v3 = __uint_as_float(f2tf(v3));
            }
            C[(size_t)r * ldc + c]           = v0;
            C[(size_t)r * ldc + c + 1]       = v1;
            C[(size_t)(r + 8) * ldc + c]     = v2;
            C[(size_t)(r + 8) * ldc + c + 1] = v3;
        }
    }
}

// ---------------------------------------------------------------------------
// Fused flash attention. 512 threads, 16 warps, 256 query rows per block.
// Q/K/V already tf32 bits (written by the projection GEMMs). ctx out: tf32.
// Warp w owns query rows [16w,16w+16). Q staging smem is reused as P patches.
// ---------------------------------------------------------------------------
static constexpr int FA_LDK = 68;   // K smem row stride (words)
static constexpr int FA_LDV = 72;   // V smem row stride (words)
static constexpr int FA_QROWS = 256;
static constexpr int FA_SMEM =
    (2 * 64 * FA_LDK + 2 * 64 * FA_LDV + FA_QROWS * FA_LDK) * 4;  // 141312 B

__global__ void __launch_bounds__(512)
fa_kernel(const float* __restrict__ Q, const float* __restrict__ K,
          const float* __restrict__ V, float* __restrict__ C)
{
    constexpr int NIT = SEQ / 64;   // 32 key tiles
    extern __shared__ float smem[];
    float* sK  = smem;                          // [2][64][FA_LDK]
    float* sV  = smem + 2 * 64 * FA_LDK;        // [2][64][FA_LDV]
    float* sQP = smem + 2 * 64 * FA_LDK + 2 * 64 * FA_LDV;  // [256][FA_LDK]

    const int z = blockIdx.y;
    const int b = z >> 4, h = z & 15;
    const int q0 = blockIdx.x * FA_QROWS;
    const float* Qg = Q + ((size_t)(b * SEQ + q0)) * 1024 + h * 64;
    const float* Kg = K + ((size_t)(b * SEQ)) * 1024 + h * 64;
    const float* Vg = V + ((size_t)(b * SEQ)) * 1024 + h * 64;

    const int tid = threadIdx.x, w = tid >> 5, l = tid & 31;
    const int lr = l >> 2, lq = l & 3;

    auto loadKV = [&](int n0, int buf) {
        float* dK = sK + buf * 64 * FA_LDK;
        float* dV = sV + buf * 64 * FA_LDV;
        #pragma unroll
        for (int i = 0; i < 2; i++) {           // 64 rows x 16 chunks = 1024
            int idx = tid + i * 512;
            int r = idx >> 4, c = (idx & 15) * 4;
            cp16(&dK[r * FA_LDK + c], Kg + (size_t)(n0 + r) * 1024 + c);
        }
        #pragma unroll
        for (int i = 0; i < 2; i++) {
            int idx = tid + i * 512;
            int r = idx >> 4, c = (idx & 15) * 4;
            cp16(&dV[r * FA_LDV + c], Vg + (size_t)(n0 + r) * 1024 + c);
        }
    };

    // Prologue: Q tile + first K/V tile
    #pragma unroll
    for (int i = 0; i < 8; i++) {               // 256 rows x 16 chunks = 4096
        int idx = tid + i * 512;
        int r = idx >> 4, c = (idx & 15) * 4;
        cp16(&sQP[r * FA_LDK + c], Qg + (size_t)r * 1024 + c);
    }
    cp_commit();
    loadKV(0, 0);
    cp_commit();

    cp_wait<1>();                                // Q ready
    __syncthreads();

    // Q fragments (already tf32 bits)
    const uint32_t* sQPu_r = (const uint32_t*)sQP;
    uint32_t qf[8][4];
    #pragma unroll
    for (int t = 0; t < 8; t++) {
        int r = w * 16 + lr, c = t * 8 + lq;
        qf[t][0] = sQPu_r[r * FA_LDK + c];
        qf[t][1] = sQPu_r[(r + 8) * FA_LDK + c];
        qf[t][2] = sQPu_r[r * FA_LDK + c + 4];
        qf[t][3] = sQPu_r[(r + 8) * FA_LDK + c + 4];
    }

    float oacc[8][4];
    #pragma unroll
    for (int j = 0; j < 8; j++)
        #pragma unroll
        for (int q = 0; q < 4; q++) oacc[j][q] = 0.f;
    float mA = -1e30f, mB = -1e30f, lA = 0.f, lB = 0.f;

    // Per-warp P patch overlaid on the (now consumed) Q staging rows
    float* sP = sQP + (size_t)w * 16 * FA_LDK;
    uint32_t* sPu = (uint32_t*)sP;

    for (int it = 0; it < NIT; it++) {
        const int buf = it & 1;
        __syncthreads();                         // everyone done with buf^1
        if (it + 1 < NIT) {
            loadKV((it + 1) * 64, buf ^ 1);
            cp_commit();
            cp_wait<1>();
        } else {
            cp_wait<0>();
        }
        __syncthreads();

        const uint32_t* cK = (const uint32_t*)(sK + buf * 64 * FA_LDK);
        const uint32_t* cV = (const uint32_t*)(sV + buf * 64 * FA_LDV);

        // S = Q * K^T  (16 rows x 64 keys per warp)
        float s[8][4];
        #pragma unroll
        for (int j = 0; j < 8; j++)
            #pragma unroll
            for (int q = 0; q < 4; q++) s[j][q] = 0.f;
        #pragma unroll
        for (int ks = 0; ks < 8; ks++) {
            #pragma unroll
            for (int j = 0; j < 8; j++) {
                uint32_t bf[2];
                bf[0] = cK[(j * 8 + lr) * FA_LDK + ks * 8 + lq];
                bf[1] = cK[(j * 8 + lr) * FA_LDK + ks * 8 + lq + 4];
                mma8(s[j], qf[ks], bf);
            }
        }

        // Online softmax (rowA = lr, rowB = lr+8 within warp tile)
        float tmA = s[0][0], tmB = s[0][2];
        #pragma unroll
        for (int j = 0; j < 8; j++) {
            tmA = fmaxf(tmA, fmaxf(s[j][0], s[j][1]));
            tmB = fmaxf(tmB, fmaxf(s[j][2], s[j][3]));
        }
        tmA = fmaxf(tmA, __shfl_xor_sync(0xffffffffu, tmA, 1));
        tmA = fmaxf(tmA, __shfl_xor_sync(0xffffffffu, tmA, 2));
        tmB = fmaxf(tmB, __shfl_xor_sync(0xffffffffu, tmB, 1));
        tmB = fmaxf(tmB, __shfl_xor_sync(0xffffffffu, tmB, 2));

        float nmA = fmaxf(mA, tmA), nmB = fmaxf(mB, tmB);
        float sclA = __expf(mA - nmA), sclB = __expf(mB - nmB);
        mA = nmA; mB = nmB;

        float sumA = 0.f, sumB = 0.f;
        #pragma unroll
        for (int j = 0; j < 8; j++) {
            float p0 = __expf(s[j][0] - nmA);
            float p1 = __expf(s[j][1] - nmA);
            float p2 = __expf(s[j][2] - nmB);
            float p3 = __expf(s[j][3] - nmB);
            sumA += p0 + p1; sumB += p2 + p3;
            *(uint2*)&sP[lr * FA_LDK + j * 8 + 2 * lq] =
                make_uint2(f2tf(p0), f2tf(p1));
            *(uint2*)&sP[(lr + 8) * FA_LDK + j * 8 + 2 * lq] =
                make_uint2(f2tf(p2), f2tf(p3));
        }
        sumA += __shfl_xor_sync(0xffffffffu, sumA, 1);
        sumA += __shfl_xor_sync(0xffffffffu, sumA, 2);
        sumB += __shfl_xor_sync(0xffffffffu, sumB, 1);
        sumB += __shfl_xor_sync(0xffffffffu, sumB, 2);
        lA = lA * sclA + sumA;
        lB = lB * sclB + sumB;

        // Rescale O accumulators
        #pragma unroll
        for (int j = 0; j < 8; j++) {
            oacc[j][0] *= sclA; oacc[j][1] *= sclA;
            oacc[j][2] *= sclB; oacc[j][3] *= sclB;
        }
        __syncwarp();

        // O += P * V   (k dim = 64 keys)
        #pragma unroll
        for (int ks = 0; ks < 8; ks++) {
            uint32_t pa[4];
            pa[0] = sPu[lr * FA_LDK + ks * 8 + lq];
            pa[1] = sPu[(lr + 8) * FA_LDK + ks * 8 + lq];
            pa[2] = sPu[lr * FA_LDK + ks * 8 + lq + 4];
            pa[3] = sPu[(lr + 8) * FA_LDK + ks * 8 + lq + 4];
            #pragma unroll
            for (int j = 0; j < 8; j++) {
                uint32_t bf[2];
                bf[0] = cV[(ks * 8 + lq) * FA_LDV + j * 8 + lr];
                bf[1] = cV[(ks * 8 + lq + 4) * FA_LDV + j * 8 + lr];
                mma8(oacc[j], pa, bf);
            }
        }
    }

    // Epilogue: normalize, write ctx as tf32 bits (Wo GEMM A-operand)
    const float invA = 1.f / lA, invB = 1.f / lB;
    const size_t rowA = (size_t)(b * SEQ + q0 + w * 16 + lr);
    #pragma unroll
    for (int j = 0; j < 8; j++) {
        int col = h * 64 + j * 8 + 2 * lq;
        *(uint2*)&C[rowA * 1024 + col] =
            make_uint2(f2tf(oacc[j][0] * invA), f2tf(oacc[j][1] * invA));
        *(uint2*)&C[(rowA + 8) * 1024 + col] =
            make_uint2(f2tf(oacc[j][2] * invB), f2tf(oacc[j][3] * invB));
    }
}

// ---------------------------------------------------------------------------
// out = LayerNorm(X + R) * g + b, rows of 1024. One block (256 thr) per row.
// Optionally also writes a tf32-bits shadow copy (GEMM A-operand).
// ---------------------------------------------------------------------------
__global__ void __launch_bounds__(256)
add_ln1024(const float* __restrict__ X, const float* __restrict__ R,
           const float* __restrict__ gam, const float* __restrict__ bet,
           float* __restrict__ O, float* __restrict__ Ot)
{
    size_t row = blockIdx.x;
    const int t = threadIdx.x;
    float4 a = ((const float4*)(X + row * 1024))[t];
    float4 r = ((const float4*)(R + row * 1024))[t];
    float4 s;
    s.x = a.x + r.x; s.y = a.y + r.y; s.z = a.z + r.z; s.w = a.w + r.w;
    float sum = s.x + s.y + s.z + s.w;
    float sq  = s.x * s.x + s.y * s.y + s.z * s.z + s.w * s.w;
    sum = bred_sum(sum);
    sq  = bred_sum(sq);
    const float mu  = sum * (1.f / 1024.f);
    const float var = sq * (1.f / 1024.f) - mu * mu;
    const float rs  = rsqrtf(var + 1e-5f);
    float4 g4 = ((const float4*)gam)[t];
    float4 b4 = ((const float4*)bet)[t];
    float4 o;
    o.x = (s.x - mu) * rs * g4.x + b4.x;
    o.y = (s.y - mu) * rs * g4.y + b4.y;
    o.z = (s.z - mu) * rs * g4.z + b4.z;
    o.w = (s.w - mu) * rs * g4.w + b4.w;
    ((float4*)(O + row * 1024))[t] = o;
    if (Ot) {
        uint4 u;
        u.x = f2tf(o.x); u.y = f2tf(o.y); u.z = f2tf(o.z); u.w = f2tf(o.w);
        ((uint4*)(Ot + row * 1024))[t] = u;
    }
}

// ---------------------------------------------------------------------------
// Launch
// ---------------------------------------------------------------------------
extern "C" void kernel_launch(void* const* d_in, const int* in_sizes, int n_in,
                              void* d_out, int out_size)
{
    (void)in_sizes; (void)n_in; (void)out_size;
    const float* src = (const float*)d_in[0];
    const float* Wq  = (const float*)d_in[1];
    const float* bq  = (const float*)d_in[2];
    const float* Wk  = (const float*)d_in[3];
    const float* bk  = (const float*)d_in[4];
    const float* Wv  = (const float*)d_in[5];
    const float* bv  = (const float*)d_in[6];
    const float* Wo  = (const float*)d_in[7];
    const float* bo  = (const float*)d_in[8];
    const float* W1  = (const float*)d_in[9];
    const float* b1  = (const float*)d_in[10];
    const float* W2  = (const float*)d_in[11];
    const float* b2  = (const float*)d_in[12];
    const float* ln1g = (const float*)d_in[13];
    const float* ln1b = (const float*)d_in[14];
    const float* ln2g = (const float*)d_in[15];
    const float* ln2b = (const float*)d_in[16];
    float* out = (float*)d_out;

    float *srcT, *WqT, *WkT, *WvT, *WoT, *W1T, *W2T;
    float *Q, *K, *V, *C, *AO, *X1, *X1T, *H, *FF;
    cudaGetSymbolAddress((void**)&srcT, g_srcT);
    cudaGetSymbolAddress((void**)&WqT, g_WqT);
    cudaGetSymbolAddress((void**)&WkT, g_WkT);
    cudaGetSymbolAddress((void**)&WvT, g_WvT);
    cudaGetSymbolAddress((void**)&WoT, g_WoT);
    cudaGetSymbolAddress((void**)&W1T, g_W1T);
    cudaGetSymbolAddress((void**)&W2T, g_W2T);
    cudaGetSymbolAddress((void**)&Q,   g_Q);
    cudaGetSymbolAddress((void**)&K,   g_K);
    cudaGetSymbolAddress((void**)&V,   g_V);
    cudaGetSymbolAddress((void**)&C,   g_C);
    cudaGetSymbolAddress((void**)&AO,  g_AO);
    cudaGetSymbolAddress((void**)&X1,  g_X1);
    cudaGetSymbolAddress((void**)&X1T, g_X1T);
    cudaGetSymbolAddress((void**)&H,   g_H);
    cudaGetSymbolAddress((void**)&FF,  g_FF);

    auto kn   = gemm_t<128, 128, 32, 32, 64, false, false>;  // fp32 out
    auto knT  = gemm_t<128, 128, 32, 32, 64, false, true>;   // tf32 out
    auto knrT = gemm_t<128, 128, 32, 32, 64, true,  true>;   // relu + tf32 out

    const int SM_KN = (128 * 36 + 32 * 136) * 2 * 4;  // 71680 B
    cudaFuncSetAttribute(kn,   cudaFuncAttributeMaxDynamicSharedMemorySize, SM_KN);
    cudaFuncSetAttribute(knT,  cudaFuncAttributeMaxDynamicSharedMemorySize, SM_KN);
    cudaFuncSetAttribute(knrT, cudaFuncAttributeMaxDynamicSharedMemorySize, SM_KN);
    cudaFuncSetAttribute(fa_kernel, cudaFuncAttributeMaxDynamicSharedMemorySize, FA_SMEM);

    const dim3 blk(256);

    // Pre-convert src + weights to tf32 bits
    cvt_tf32<<<256, blk>>>(src, srcT, TOK * DMODEL / 4);
    cvt_tf32<<<128, blk>>>(Wq, WqT, DMODEL * DMODEL / 4);
    cvt_tf32<<<128, blk>>>(Wk, WkT, DMODEL * DMODEL / 4);
    cvt_tf32<<<128, blk>>>(Wv, WvT, DMODEL * DMODEL / 4);
    cvt_tf32<<<128, blk>>>(Wo, WoT, DMODEL * DMODEL / 4);
    cvt_tf32<<<256, blk>>>(W1, W1T, DMODEL * DFFN / 4);
    cvt_tf32<<<256, blk>>>(W2, W2T, DFFN * DMODEL / 4);

    // QKV projections -> tf32 outputs (Q pre-scaled by 1/sqrt(d_k))
    knT<<<dim3(8, 32), blk, SM_KN>>>(srcT, WqT, bq, Q, 1024, 1024, 1024, 1024, 0.125f);
    knT<<<dim3(8, 32), blk, SM_KN>>>(srcT, WkT, bk, K, 1024, 1024, 1024, 1024, 1.f);
    knT<<<dim3(8, 32), blk, SM_KN>>>(srcT, WvT, bv, V, 1024, 1024, 1024, 1024, 1.f);

    // Fused attention -> tf32 ctx
    fa_kernel<<<dim3(8, 32), dim3(512), FA_SMEM>>>(Q, K, V, C);

    // attn_out = ctx * Wo + bo  (fp32 out)
    kn<<<dim3(8, 32), blk, SM_KN>>>(C, WoT, bo, AO, 1024, 1024, 1024, 1024, 1.f);

    // x1 = LN(src + attn_out)  (fp32 + tf32 shadow)
    add_ln1024<<<4096, blk>>>(src, AO, ln1g, ln1b, X1, X1T);

    // h = relu(x1 * W1 + b1)  -> tf32
    knrT<<<dim3(32, 32), blk, SM_KN>>>(X1T, W1T, b1, H, 1024, 1024, 4096, 4096, 1.f);

    // ff = h * W2 + b2  (fp32 out)
    kn<<<dim3(8, 32), blk, SM_KN>>>(H, W2T, b2, FF, 4096, 4096, 1024, 1024, 1.f);

    // out = LN(x1 + ff)
    add_ln1024<<<4096, blk>>>(X1, FF, ln2g, ln2b, out, nullptr);
}

// round 5
// speedup vs baseline: 2.4556x; 1.8655x over previous
#include <cuda_runtime.h>
#include <cuda_bf16.h>
#include <cstdint>

// Problem constants
static constexpr int TOK    = 4096;   // B*S
static constexpr int SEQ    = 2048;
static constexpr int DMODEL = 1024;
static constexpr int DFFN   = 4096;

// ---------------------------------------------------------------------------
// Device scratch (allocation-free rule: __device__ globals)
// ---------------------------------------------------------------------------
__device__ __nv_bfloat16 g_srcB[(size_t)TOK * DMODEL];
__device__ __nv_bfloat16 g_WqB [(size_t)DMODEL * DMODEL];
__device__ __nv_bfloat16 g_WkB [(size_t)DMODEL * DMODEL];
__device__ __nv_bfloat16 g_WvB [(size_t)DMODEL * DMODEL];
__device__ __nv_bfloat16 g_WoB [(size_t)DMODEL * DMODEL];
__device__ __nv_bfloat16 g_W1B [(size_t)DMODEL * DFFN];
__device__ __nv_bfloat16 g_W2B [(size_t)DFFN * DMODEL];
__device__ __nv_bfloat16 g_Q   [(size_t)TOK * DMODEL];
__device__ __nv_bfloat16 g_K   [(size_t)TOK * DMODEL];
__device__ __nv_bfloat16 g_V   [(size_t)TOK * DMODEL];
__device__ __nv_bfloat16 g_C   [(size_t)TOK * DMODEL];   // ctx (bf16)
__device__ __nv_bfloat16 g_X1B [(size_t)TOK * DMODEL];   // bf16 LN1 out
__device__ __nv_bfloat16 g_H   [(size_t)TOK * DFFN];     // bf16 relu(xW1+b1)
__device__ float g_AO[(size_t)TOK * DMODEL];             // fp32 attn_out
__device__ float g_X1[(size_t)TOK * DMODEL];             // fp32 LN1 out
__device__ float g_FF[(size_t)TOK * DMODEL];             // fp32 ff out

// ---------------------------------------------------------------------------
// Helpers
// ---------------------------------------------------------------------------
__device__ __forceinline__ uint32_t packbf(float lo, float hi) {
    uint32_t r;
    asm("cvt.rn.bf16x2.f32 %0, %1, %2;" : "=r"(r) : "f"(hi), "f"(lo));
    return r;
}
__device__ __forceinline__ void cp16(void* s, const void* g) {
    uint32_t sa = (uint32_t)__cvta_generic_to_shared(s);
    asm volatile("cp.async.cg.shared.global [%0], [%1], 16;" :: "r"(sa), "l"(g));
}
__device__ __forceinline__ void cp_commit() { asm volatile("cp.async.commit_group;"); }
template <int N> __device__ __forceinline__ void cp_wait() {
    asm volatile("cp.async.wait_group %0;" :: "n"(N));
}
__device__ __forceinline__ void ldsm4(uint32_t* r, const void* p) {
    uint32_t a = (uint32_t)__cvta_generic_to_shared(p);
    asm volatile("ldmatrix.sync.aligned.m8n8.x4.shared.b16 {%0,%1,%2,%3}, [%4];"
                 : "=r"(r[0]), "=r"(r[1]), "=r"(r[2]), "=r"(r[3]) : "r"(a));
}
__device__ __forceinline__ void ldsm4t(uint32_t* r, const void* p) {
    uint32_t a = (uint32_t)__cvta_generic_to_shared(p);
    asm volatile("ldmatrix.sync.aligned.m8n8.x4.trans.shared.b16 {%0,%1,%2,%3}, [%4];"
                 : "=r"(r[0]), "=r"(r[1]), "=r"(r[2]), "=r"(r[3]) : "r"(a));
}
__device__ __forceinline__ void mma16(float* c, const uint32_t* a, const uint32_t* b) {
    asm volatile(
        "mma.sync.aligned.m16n8k16.row.col.f32.bf16.bf16.f32 "
        "{%0,%1,%2,%3},{%4,%5,%6,%7},{%8,%9},{%0,%1,%2,%3};"
        : "+f"(c[0]), "+f"(c[1]), "+f"(c[2]), "+f"(c[3])
        : "r"(a[0]), "r"(a[1]), "r"(a[2]), "r"(a[3]), "r"(b[0]), "r"(b[1]));
}

// Block-wide sum over 256 threads (8 warps)
__device__ __forceinline__ float bred_sum(float v) {
    __shared__ float sh[8];
    #pragma unroll
    for (int o = 16; o > 0; o >>= 1) v += __shfl_xor_sync(0xffffffffu, v, o);
    if ((threadIdx.x & 31) == 0) sh[threadIdx.x >> 5] = v;
    __syncthreads();
    float r = sh[0];
    #pragma unroll
    for (int i = 1; i < 8; i++) r += sh[i];
    __syncthreads();
    return r;
}

// ---------------------------------------------------------------------------
// fp32 -> bf16 converter (vectorized, grid-stride)
// ---------------------------------------------------------------------------
__global__ void __launch_bounds__(256)
cvt_bf16(const float* __restrict__ in, __nv_bfloat16* __restrict__ out, int n4)
{
    for (int i = blockIdx.x * 256 + threadIdx.x; i < n4; i += gridDim.x * 256) {
        float4 v = ((const float4*)in)[i];
        uint2 u;
        u.x = packbf(v.x, v.y);
        u.y = packbf(v.z, v.w);
        ((uint2*)out)[i] = u;
    }
}

// ---------------------------------------------------------------------------
// BF16 GEMM.  C[M,N] = epi( A[M,K]*B + bias ).  A row-major, B [K,N] row-major.
// BM=128 BN=128 BK=64, 8 warps (WM=32, WN=64), 2 CTAs/SM.
// A frags: ldmatrix.x4 (non-trans); B frags: ldmatrix.x4.trans.
// OBF: write bf16 pairs; else fp32.
// ---------------------------------------------------------------------------
static constexpr int G_LDA = 72;    // A smem row stride (bf16), 144B
static constexpr int G_LDB = 136;   // B smem row stride, 272B
static constexpr int G_ASZ = 128 * G_LDA;
static constexpr int G_BSZ = 64 * G_LDB;
static constexpr int G_SMEM = (G_ASZ + G_BSZ) * 2 * 2;  // 71680 B

template <bool RELU, bool OBF>
__global__ void __launch_bounds__(256, 2)
gemm_b(const __nv_bfloat16* __restrict__ A, const __nv_bfloat16* __restrict__ B,
       const float* __restrict__ bias, void* __restrict__ Cv,
       int Kdim, int lda, int ldb, int ldc, float alpha)
{
    extern __shared__ __align__(16) __nv_bfloat16 smem[];
    __nv_bfloat16* sA = smem;
    __nv_bfloat16* sB = smem + 2 * G_ASZ;

    const int m0 = blockIdx.y * 128, n0 = blockIdx.x * 128;
    const int tid = threadIdx.x, w = tid >> 5, l = tid & 31;
    const int wm = (w & 3) * 32, wn = (w >> 2) * 64;
    const int g = l >> 3, i8 = l & 7;
    const int lr = l >> 2, lq = l & 3;

    float acc[2][8][4];
    #pragma unroll
    for (int i = 0; i < 2; i++)
        #pragma unroll
        for (int j = 0; j < 8; j++)
            #pragma unroll
            for (int q = 0; q < 4; q++) acc[i][j][q] = 0.f;

    const int KT = Kdim / 64;

    auto load_tiles = [&](int kt, int buf) {
        {   // A tile [128][64]
            const __nv_bfloat16* gA = A + (size_t)m0 * lda + kt * 64;
            __nv_bfloat16* s = sA + buf * G_ASZ;
            #pragma unroll
            for (int i = 0; i < 4; i++) {
                int idx = tid + i * 256;
                int r = idx >> 3, c = (idx & 7) * 8;
                cp16(&s[r * G_LDA + c], gA + (size_t)r * lda + c);
            }
        }
        {   // B tile [64][128]
            const __nv_bfloat16* gB = B + (size_t)kt * 64 * ldb + n0;
            __nv_bfloat16* s = sB + buf * G_BSZ;
            #pragma unroll
            for (int i = 0; i < 4; i++) {
                int idx = tid + i * 256;
                int r = idx >> 4, c = (idx & 15) * 8;
                cp16(&s[r * G_LDB + c], gB + (size_t)r * ldb + c);
            }
        }
    };

    load_tiles(0, 0);
    cp_commit();

    for (int kt = 0; kt < KT; kt++) {
        const int buf = kt & 1;
        if (kt + 1 < KT) {
            load_tiles(kt + 1, buf ^ 1);
            cp_commit();
            cp_wait<1>();
        } else {
            cp_wait<0>();
        }
        __syncthreads();

        const __nv_bfloat16* cA = sA + buf * G_ASZ;
        const __nv_bfloat16* cB = sB + buf * G_BSZ;
        #pragma unroll
        for (int t = 0; t < 4; t++) {
            uint32_t af[2][4], bf[4][4];
            #pragma unroll
            for (int i = 0; i < 2; i++) {
                int r = wm + i * 16 + (g & 1) * 8 + i8;
                int c = t * 16 + (g >> 1) * 8;
                ldsm4(af[i], &cA[r * G_LDA + c]);
            }
            #pragma unroll
            for (int p = 0; p < 4; p++) {
                int r = t * 16 + (g & 1) * 8 + i8;
                int c = wn + p * 16 + (g >> 1) * 8;
                ldsm4t(bf[p], &cB[r * G_LDB + c]);
            }
            #pragma unroll
            for (int i = 0; i < 2; i++)
                #pragma unroll
                for (int p = 0; p < 4; p++) {
                    mma16(acc[i][2 * p],     af[i], &bf[p][0]);
                    mma16(acc[i][2 * p + 1], af[i], &bf[p][2]);
                }
        }
        __syncthreads();
    }

    // Epilogue
    #pragma unroll
    for (int i = 0; i < 2; i++) {
        #pragma unroll
        for (int j = 0; j < 8; j++) {
            int r = m0 + wm + i * 16 + lr;
            int c = n0 + wn + j * 8 + lq * 2;
            float b0 = bias ? bias[c] : 0.f;
            float b1 = bias ? bias[c + 1] : 0.f;
            float v0 = (acc[i][j][0] + b0) * alpha;
            float v1 = (acc[i][j][1] + b1) * alpha;
            float v2 = (acc[i][j][2] + b0) * alpha;
            float v3 = (acc[i][j][3] + b1) * alpha;
            if constexpr (RELU) {
                v0 = fmaxf(v0, 0.f); v1 = fmaxf(v1, 0.f);
                v2 = fmaxf(v2, 0.f); v3 = fmaxf(v3, 0.f);
            }
            if constexpr (OBF) {
                __nv_bfloat16* Cb = (__nv_bfloat16*)Cv;
                *(uint32_t*)&Cb[(size_t)r * ldc + c]       = packbf(v0, v1);
                *(uint32_t*)&Cb[(size_t)(r + 8) * ldc + c] = packbf(v2, v3);
            } else {
                float* Cf = (float*)Cv;
                Cf[(size_t)r * ldc + c]           = v0;
                Cf[(size_t)r * ldc + c + 1]       = v1;
                Cf[(size_t)(r + 8) * ldc + c]     = v2;
                Cf[(size_t)(r + 8) * ldc + c + 1] = v3;
            }
        }
    }
}

// ---------------------------------------------------------------------------
// Fused flash attention (bf16). 512 threads / 16 warps, 256 q-rows per block.
// Warp w owns rows [16w,16w+16). P stays in registers (S-frag == A-frag layout).
// ---------------------------------------------------------------------------
static constexpr int FA_LD = 72;    // smem row stride (bf16) for Q/K/V
static constexpr int FA_SMEM = (2 * 64 * FA_LD + 2 * 64 * FA_LD + 256 * FA_LD) * 2;

__global__ void __launch_bounds__(512)
fa_kernel(const __nv_bfloat16* __restrict__ Q, const __nv_bfloat16* __restrict__ K,
          const __nv_bfloat16* __restrict__ V, __nv_bfloat16* __restrict__ C)
{
    constexpr int NIT = SEQ / 64;   // 32 key tiles
    extern __shared__ __align__(16) __nv_bfloat16 smem[];
    __nv_bfloat16* sK = smem;                        // [2][64][FA_LD]
    __nv_bfloat16* sV = smem + 2 * 64 * FA_LD;       // [2][64][FA_LD]
    __nv_bfloat16* sQ = smem + 4 * 64 * FA_LD;       // [256][FA_LD]

    const int z = blockIdx.y;
    const int b = z >> 4, h = z & 15;
    const int q0 = blockIdx.x * 256;
    const __nv_bfloat16* Qg = Q + ((size_t)(b * SEQ + q0)) * 1024 + h * 64;
    const __nv_bfloat16* Kg = K + ((size_t)(b * SEQ)) * 1024 + h * 64;
    const __nv_bfloat16* Vg = V + ((size_t)(b * SEQ)) * 1024 + h * 64;

    const int tid = threadIdx.x, w = tid >> 5, l = tid & 31;
    const int g = l >> 3, i8 = l & 7;
    const int lr = l >> 2, lq = l & 3;

    auto loadKV = [&](int n0, int buf) {
        __nv_bfloat16* dK = sK + buf * 64 * FA_LD;
        __nv_bfloat16* dV = sV + buf * 64 * FA_LD;
        {   // 64 rows x 8 chunks = 512
            int r = tid >> 3, c = (tid & 7) * 8;
            cp16(&dK[r * FA_LD + c], Kg + (size_t)(n0 + r) * 1024 + c);
            cp16(&dV[r * FA_LD + c], Vg + (size_t)(n0 + r) * 1024 + c);
        }
    };

    // Prologue: Q tile + first K/V tile
    #pragma unroll
    for (int i = 0; i < 4; i++) {       // 256 rows x 8 chunks = 2048
        int idx = tid + i * 512;
        int r = idx >> 3, c = (idx & 7) * 8;
        cp16(&sQ[r * FA_LD + c], Qg + (size_t)r * 1024 + c);
    }
    cp_commit();
    loadKV(0, 0);
    cp_commit();

    cp_wait<1>();                        // Q ready
    __syncthreads();

    // Q fragments: 4 k-blocks of 16
    uint32_t qf[4][4];
    #pragma unroll
    for (int t = 0; t < 4; t++) {
        int r = w * 16 + (g & 1) * 8 + i8;
        int c = t * 16 + (g >> 1) * 8;
        ldsm4(qf[t], &sQ[r * FA_LD + c]);
    }

    float oacc[8][4];
    #pragma unroll
    for (int j = 0; j < 8; j++)
        #pragma unroll
        for (int q = 0; q < 4; q++) oacc[j][q] = 0.f;
    float mA = -1e30f, mB = -1e30f, lA = 0.f, lB = 0.f;

    for (int it = 0; it < NIT; it++) {
        const int buf = it & 1;
        __syncthreads();                 // everyone done with buf^1
        if (it + 1 < NIT) {
            loadKV((it + 1) * 64, buf ^ 1);
            cp_commit();
            cp_wait<1>();
        } else {
            cp_wait<0>();
        }
        __syncthreads();

        const __nv_bfloat16* cK = sK + buf * 64 * FA_LD;
        const __nv_bfloat16* cV = sV + buf * 64 * FA_LD;

        // S = Q * K^T : s[j] covers keys j*8..j*8+7 (cols), rows lr / lr+8
        float s[8][4];
        #pragma unroll
        for (int j = 0; j < 8; j++)
            #pragma unroll
            for (int q = 0; q < 4; q++) s[j][q] = 0.f;
        #pragma unroll
        for (int t = 0; t < 4; t++) {
            #pragma unroll
            for (int jp = 0; jp < 4; jp++) {
                uint32_t kf[4];
                int r = jp * 16 + (g >> 1) * 8 + i8;   // key row
                int c = t * 16 + (g & 1) * 8;          // dim col
                ldsm4(kf, &cK[r * FA_LD + c]);
                mma16(s[2 * jp],     qf[t], &kf[0]);
                mma16(s[2 * jp + 1], qf[t], &kf[2]);
            }
        }

        // Online softmax (rows lr and lr+8 of warp tile)
        float tmA = s[0][0], tmB = s[0][2];
        #pragma unroll
        for (int j = 0; j < 8; j++) {
            tmA = fmaxf(tmA, fmaxf(s[j][0], s[j][1]));
            tmB = fmaxf(tmB, fmaxf(s[j][2], s[j][3]));
        }
        tmA = fmaxf(tmA, __shfl_xor_sync(0xffffffffu, tmA, 1));
        tmA = fmaxf(tmA, __shfl_xor_sync(0xffffffffu, tmA, 2));
        tmB = fmaxf(tmB, __shfl_xor_sync(0xffffffffu, tmB, 1));
        tmB = fmaxf(tmB, __shfl_xor_sync(0xffffffffu, tmB, 2));

        float nmA = fmaxf(mA, tmA), nmB = fmaxf(mB, tmB);
        float sclA = __expf(mA - nmA), sclB = __expf(mB - nmB);
        mA = nmA; mB = nmB;

        float sumA = 0.f, sumB = 0.f;
        #pragma unroll
        for (int j = 0; j < 8; j++) {
            s[j][0] = __expf(s[j][0] - nmA);
            s[j][1] = __expf(s[j][1] - nmA);
            s[j][2] = __expf(s[j][2] - nmB);
            s[j][3] = __expf(s[j][3] - nmB);
            sumA += s[j][0] + s[j][1];
            sumB += s[j][2] + s[j][3];
        }
        sumA += __shfl_xor_sync(0xffffffffu, sumA, 1);
        sumA += __shfl_xor_sync(0xffffffffu, sumA, 2);
        sumB += __shfl_xor_sync(0xffffffffu, sumB, 1);
        sumB += __shfl_xor_sync(0xffffffffu, sumB, 2);
        lA = lA * sclA + sumA;
        lB = lB * sclB + sumB;

        #pragma unroll
        for (int j = 0; j < 8; j++) {
            oacc[j][0] *= sclA; oacc[j][1] *= sclA;
            oacc[j][2] *= sclB; oacc[j][3] *= sclB;
        }

        // O += P * V.  P A-frags packed straight from S fragments.
        #pragma unroll
        for (int t = 0; t < 4; t++) {
            uint32_t pa[4];
            pa[0] = packbf(s[2 * t][0],     s[2 * t][1]);
            pa[1] = packbf(s[2 * t][2],     s[2 * t][3]);
            pa[2] = packbf(s[2 * t + 1][0], s[2 * t + 1][1]);
            pa[3] = packbf(s[2 * t + 1][2], s[2 * t + 1][3]);
            #pragma unroll
            for (int jp = 0; jp < 4; jp++) {
                uint32_t vf[4];
                int r = t * 16 + (g & 1) * 8 + i8;     // key row
                int c = jp * 16 + (g >> 1) * 8;        // dim col
                ldsm4t(vf, &cV[r * FA_LD + c]);
                mma16(oacc[2 * jp],     pa, &vf[0]);
                mma16(oacc[2 * jp + 1], pa, &vf[2]);
            }
        }
    }

    // Epilogue: normalize, write bf16 ctx (token-major, head-contig cols)
    const float invA = 1.f / lA, invB = 1.f / lB;
    const size_t rowA = (size_t)(b * SEQ + q0 + w * 16 + lr);
    #pragma unroll
    for (int j = 0; j < 8; j++) {
        int col = h * 64 + j * 8 + 2 * lq;
        *(uint32_t*)&C[rowA * 1024 + col] =
            packbf(oacc[j][0] * invA, oacc[j][1] * invA);
        *(uint32_t*)&C[(rowA + 8) * 1024 + col] =
            packbf(oacc[j][2] * invB, oacc[j][3] * invB);
    }
}

// ---------------------------------------------------------------------------
// out = LayerNorm(X + R) * g + b, rows of 1024. One block (256 thr) per row.
// Optionally also writes a bf16 shadow copy (GEMM A-operand).
// ---------------------------------------------------------------------------
__global__ void __launch_bounds__(256)
add_ln1024(const float* __restrict__ X, const float* __restrict__ R,
           const float* __restrict__ gam, const float* __restrict__ bet,
           float* __restrict__ O, __nv_bfloat16* __restrict__ Ob)
{
    size_t row = blockIdx.x;
    const int t = threadIdx.x;
    float4 a = ((const float4*)(X + row * 1024))[t];
    float4 r = ((const float4*)(R + row * 1024))[t];
    float4 s;
    s.x = a.x + r.x; s.y = a.y + r.y; s.z = a.z + r.z; s.w = a.w + r.w;
    float sum = s.x + s.y + s.z + s.w;
    float sq  = s.x * s.x + s.y * s.y + s.z * s.z + s.w * s.w;
    sum = bred_sum(sum);
    sq  = bred_sum(sq);
    const float mu  = sum * (1.f / 1024.f);
    const float var = sq * (1.f / 1024.f) - mu * mu;
    const float rs  = rsqrtf(var + 1e-5f);
    float4 g4 = ((const float4*)gam)[t];
    float4 b4 = ((const float4*)bet)[t];
    float4 o;
    o.x = (s.x - mu) * rs * g4.x + b4.x;
    o.y = (s.y - mu) * rs * g4.y + b4.y;
    o.z = (s.z - mu) * rs * g4.z + b4.z;
    o.w = (s.w - mu) * rs * g4.w + b4.w;
    ((float4*)(O + row * 1024))[t] = o;
    if (Ob) {
        uint2 u;
        u.x = packbf(o.x, o.y);
        u.y = packbf(o.z, o.w);
        ((uint2*)(Ob + row * 1024))[t] = u;
    }
}

// ---------------------------------------------------------------------------
// Launch
// ---------------------------------------------------------------------------
extern "C" void kernel_launch(void* const* d_in, const int* in_sizes, int n_in,
                              void* d_out, int out_size)
{
    (void)in_sizes; (void)n_in; (void)out_size;
    const float* src = (const float*)d_in[0];
    const float* Wq  = (const float*)d_in[1];
    const float* bq  = (const float*)d_in[2];
    const float* Wk  = (const float*)d_in[3];
    const float* bk  = (const float*)d_in[4];
    const float* Wv  = (const float*)d_in[5];
    const float* bv  = (const float*)d_in[6];
    const float* Wo  = (const float*)d_in[7];
    const float* bo  = (const float*)d_in[8];
    const float* W1  = (const float*)d_in[9];
    const float* b1  = (const float*)d_in[10];
    const float* W2  = (const float*)d_in[11];
    const float* b2  = (const float*)d_in[12];
    const float* ln1g = (const float*)d_in[13];
    const float* ln1b = (const float*)d_in[14];
    const float* ln2g = (const float*)d_in[15];
    const float* ln2b = (const float*)d_in[16];
    float* out = (float*)d_out;

    __nv_bfloat16 *srcB, *WqB, *WkB, *WvB, *WoB, *W1B, *W2B;
    __nv_bfloat16 *Q, *K, *V, *C, *X1B, *H;
    float *AO, *X1, *FF;
    cudaGetSymbolAddress((void**)&srcB, g_srcB);
    cudaGetSymbolAddress((void**)&WqB, g_WqB);
    cudaGetSymbolAddress((void**)&WkB, g_WkB);
    cudaGetSymbolAddress((void**)&WvB, g_WvB);
    cudaGetSymbolAddress((void**)&WoB, g_WoB);
    cudaGetSymbolAddress((void**)&W1B, g_W1B);
    cudaGetSymbolAddress((void**)&W2B, g_W2B);
    cudaGetSymbolAddress((void**)&Q,   g_Q);
    cudaGetSymbolAddress((void**)&K,   g_K);
    cudaGetSymbolAddress((void**)&V,   g_V);
    cudaGetSymbolAddress((void**)&C,   g_C);
    cudaGetSymbolAddress((void**)&X1B, g_X1B);
    cudaGetSymbolAddress((void**)&H,   g_H);
    cudaGetSymbolAddress((void**)&AO,  g_AO);
    cudaGetSymbolAddress((void**)&X1,  g_X1);
    cudaGetSymbolAddress((void**)&FF,  g_FF);

    auto knF  = gemm_b<false, false>;  // fp32 out
    auto knB  = gemm_b<false, true>;   // bf16 out
    auto knrB = gemm_b<true,  true>;   // relu + bf16 out

    cudaFuncSetAttribute(knF,  cudaFuncAttributeMaxDynamicSharedMemorySize, G_SMEM);
    cudaFuncSetAttribute(knB,  cudaFuncAttributeMaxDynamicSharedMemorySize, G_SMEM);
    cudaFuncSetAttribute(knrB, cudaFuncAttributeMaxDynamicSharedMemorySize, G_SMEM);
    cudaFuncSetAttribute(fa_kernel, cudaFuncAttributeMaxDynamicSharedMemorySize, FA_SMEM);

    const dim3 blk(256);

    // Pre-convert src + weights to bf16
    cvt_bf16<<<256, blk>>>(src, srcB, TOK * DMODEL / 4);
    cvt_bf16<<<128, blk>>>(Wq, WqB, DMODEL * DMODEL / 4);
    cvt_bf16<<<128, blk>>>(Wk, WkB, DMODEL * DMODEL / 4);
    cvt_bf16<<<128, blk>>>(Wv, WvB, DMODEL * DMODEL / 4);
    cvt_bf16<<<128, blk>>>(Wo, WoB, DMODEL * DMODEL / 4);
    cvt_bf16<<<256, blk>>>(W1, W1B, DMODEL * DFFN / 4);
    cvt_bf16<<<256, blk>>>(W2, W2B, DFFN * DMODEL / 4);

    // QKV projections -> bf16 (Q pre-scaled by 1/sqrt(d_k))
    knB<<<dim3(8, 32), blk, G_SMEM>>>(srcB, WqB, bq, Q, 1024, 1024, 1024, 1024, 0.125f);
    knB<<<dim3(8, 32), blk, G_SMEM>>>(srcB, WkB, bk, K, 1024, 1024, 1024, 1024, 1.f);
    knB<<<dim3(8, 32), blk, G_SMEM>>>(srcB, WvB, bv, V, 1024, 1024, 1024, 1024, 1.f);

    // Fused attention -> bf16 ctx
    fa_kernel<<<dim3(8, 32), dim3(512), FA_SMEM>>>(Q, K, V, C);

    // attn_out = ctx * Wo + bo  (fp32 out)
    knF<<<dim3(8, 32), blk, G_SMEM>>>(C, WoB, bo, AO, 1024, 1024, 1024, 1024, 1.f);

    // x1 = LN(src + attn_out)  (fp32 + bf16 shadow)
    add_ln1024<<<4096, blk>>>(src, AO, ln1g, ln1b, X1, X1B);

    // h = relu(x1 * W1 + b1) -> bf16
    knrB<<<dim3(32, 32), blk, G_SMEM>>>(X1B, W1B, b1, H, 1024, 1024, 4096, 4096, 1.f);

    // ff = h * W2 + b2  (fp32 out)
    knF<<<dim3(8, 32), blk, G_SMEM>>>(H, W2B, b2, FF, 4096, 4096, 1024, 1024, 1.f);

    // out = LN(x1 + ff)
    add_ln1024<<<4096, blk>>>(X1, FF, ln2g, ln2b, out, nullptr);
}